// round 1
// baseline (speedup 1.0000x reference)
#include <cuda_runtime.h>

#define NCTA 128
#define NTHR 256
#define T_STEPS 512
#define BATCH 128

// Static device scratch (no allocation allowed in kernel_launch).
__device__ float g_xT[T_STEPS * BATCH * 512];   // [t][b][k], 134 MB
__device__ float g_mem0[BATCH * 1024];
__device__ float g_spk0[BATCH * 1024];
__device__ float g_mem1[BATCH * 1024];
__device__ float g_spk1[BATCH * 1024];
__device__ float g_mem2[BATCH * 512];
__device__ float g_spk2[BATCH * 512];
__device__ int          g_count;
__device__ volatile int g_gen;

// Grid-wide barrier: all NCTA CTAs are co-resident (128 <= 148 SMs, 1 CTA/SM).
// __threadfence() (gpu scope) both orders stores and emits CCTL.IVALL on
// sm_103a, invalidating stale L1 lines before post-barrier loads.
__device__ __forceinline__ void grid_sync()
{
    __threadfence();
    __syncthreads();
    if (threadIdx.x == 0) {
        int gen = g_gen;                       // read BEFORE arriving
        if (atomicAdd(&g_count, 1) == NCTA - 1) {
            g_count = 0;
            __threadfence();
            g_gen = gen + 1;                   // release
        } else {
            while (g_gen == gen) { }           // volatile spin (bypasses L1)
        }
    }
    __syncthreads();
    __threadfence();
}

// One GEMM tile + LIF state update.
// Tile: M batch rows x 256 output cols, full K. 128 tiles total per layer.
// A rows are contiguous length-K fp32 (xT rows or spike rows).
// Accumulation is a strict serial-k FFMA chain per output (fp32).
template<int M>
__device__ __forceinline__ void layer_tile(
    const float* __restrict__ A, const float* __restrict__ W,
    float* __restrict__ mem, float* __restrict__ spk,
    int K, int N, int cta, float* sA, float* sW)
{
    const int tid    = threadIdx.x;
    const int jTiles = N >> 8;                 // N / 256
    const int bBlk   = cta / jTiles;
    const int jBase  = (cta % jTiles) << 8;
    const int K4     = K >> 2;

    float4* sA4 = (float4*)sA;

    // Stage A: M rows x K floats (coalesced float4 loads).
    {
        const int totA4 = (M * K) >> 2;
        for (int i = tid; i < totA4; i += NTHR) {
            int m  = i / K4;
            int kk = i - m * K4;
            sA4[m * K4 + kk] = ((const float4*)(A + (bBlk * M + m) * K))[kk];
        }
    }

    float acc[M];
#pragma unroll
    for (int m = 0; m < M; ++m) acc[m] = 0.0f;

    for (int kc = 0; kc < K; kc += 32) {
        // Stage W chunk: 32 k-rows x 256 cols (coalesced along j).
        float4* sW4 = (float4*)sW;
#pragma unroll
        for (int i = 0; i < 8; ++i) {
            int flat = i * NTHR + tid;         // 2048 float4 total
            int r    = flat >> 6;
            int c4   = (flat & 63) << 2;
            sW4[flat] = *(const float4*)(W + (kc + r) * N + jBase + c4);
        }
        __syncthreads();

#pragma unroll
        for (int k = 0; k < 32; k += 4) {
            float wv0 = sW[(k + 0) * 256 + tid];
            float wv1 = sW[(k + 1) * 256 + tid];
            float wv2 = sW[(k + 2) * 256 + tid];
            float wv3 = sW[(k + 3) * 256 + tid];
#pragma unroll
            for (int m = 0; m < M; ++m) {
                float4 a = sA4[m * K4 + ((kc + k) >> 2)];   // broadcast LDS
                acc[m] = fmaf(a.x, wv0, acc[m]);
                acc[m] = fmaf(a.y, wv1, acc[m]);
                acc[m] = fmaf(a.z, wv2, acc[m]);
                acc[m] = fmaf(a.w, wv3, acc[m]);
            }
        }
        __syncthreads();
    }

    // LIF update: mem*0.5*(1-s) is exact (factor in {0, 0.5}); one rounded add.
    const int j = jBase + tid;
#pragma unroll
    for (int m = 0; m < M; ++m) {
        int   row = bBlk * M + m;
        float mv  = mem[row * N + j];
        float sv  = spk[row * N + j];
        float nm  = mv * (0.5f * (1.0f - sv)) + acc[m];
        mem[row * N + j] = nm;
        spk[row * N + j] = (nm > 0.3f) ? 1.0f : 0.0f;
    }
}

__global__ __launch_bounds__(NTHR, 1)
void snn_kernel(const float* __restrict__ x,
                const float* __restrict__ w0,
                const float* __restrict__ w1,
                const float* __restrict__ w2,
                float* __restrict__ out)
{
    __shared__ float sA[4096];   // 16 KB: A rows / transpose tile
    __shared__ float sW[8192];   // 32 KB: W chunk
    const int cta = blockIdx.x;
    const int tid = threadIdx.x;

    // ---- Init: zero LIF state (every launch must be deterministic) ----
    for (int i = cta * NTHR + tid; i < BATCH * 1024; i += NCTA * NTHR) {
        g_mem0[i] = 0.f; g_spk0[i] = 0.f; g_mem1[i] = 0.f; g_spk1[i] = 0.f;
    }
    for (int i = cta * NTHR + tid; i < BATCH * 512; i += NCTA * NTHR) {
        g_mem2[i] = 0.f; g_spk2[i] = 0.f;
    }

    // ---- Transpose x[b][k][t] -> g_xT[t][b][k] (32x32 smem tiles) ----
    {
        const int r = tid >> 5, c = tid & 31;
        // 128 b * 16 * 16 tiles = 32768; 256 per CTA (uniform -> sync-safe)
        for (int tile = cta; tile < BATCH * 16 * 16; tile += NCTA) {
            int b   = tile >> 8;
            int rem = tile & 255;
            int k0  = (rem >> 4) << 5;
            int t0  = (rem & 15) << 5;
            const float* src = x + b * (512 * 512);
            __syncthreads();
            for (int rr = r; rr < 32; rr += 8)
                sA[rr * 33 + c] = src[(k0 + rr) * 512 + (t0 + c)];
            __syncthreads();
            for (int rr = r; rr < 32; rr += 8)
                g_xT[(t0 + rr) * (BATCH * 512) + b * 512 + (k0 + c)] = sA[c * 33 + rr];
        }
    }
    grid_sync();

    // ---- Time loop: 2 grid syncs/step via L0(t) || L2(t-1) fusion ----
    for (int t = 0; t < T_STEPS; ++t) {
        layer_tile<4>(g_xT + t * (BATCH * 512), w0, g_mem0, g_spk0, 512, 1024, cta, sA, sW);
        if (t > 0)
            layer_tile<2>(g_spk1, w2, g_mem2, g_spk2, 1024, 512, cta, sA, sW);
        grid_sync();
        layer_tile<4>(g_spk0, w1, g_mem1, g_spk1, 1024, 1024, cta, sA, sW);
        grid_sync();
    }
    layer_tile<2>(g_spk1, w2, g_mem2, g_spk2, 1024, 512, cta, sA, sW);
    grid_sync();

    // ---- Output: layer-2 spikes at final step, [128,512] fp32 ----
    for (int i = cta * NTHR + tid; i < BATCH * 512; i += NCTA * NTHR)
        out[i] = g_spk2[i];
}

extern "C" void kernel_launch(void* const* d_in, const int* in_sizes, int n_in,
                              void* d_out, int out_size)
{
    const float* x  = (const float*)d_in[0];
    const float* w0 = (const float*)d_in[1];
    const float* w1 = (const float*)d_in[2];
    const float* w2 = (const float*)d_in[3];
    (void)in_sizes; (void)n_in; (void)out_size;
    snn_kernel<<<NCTA, NTHR>>>(x, w0, w1, w2, (float*)d_out);
}

// round 6
// speedup vs baseline: 1.0896x; 1.0896x over previous
#include <cuda_runtime.h>
#include <cstdint>

#define NCTA  128
#define NTHR  128
#define T_STEPS 512
#define BATCH 128
#define APAD  68      // staged A row: 64 floats + 4 pad (bank-conflict-free LDS.128)

// ---- global scratch (static: no allocation allowed) ----
__device__ float g_xT[T_STEPS * BATCH * 512];   // [t][b][k]  time-major input
__device__ float g_spk0[BATCH * 1024];
__device__ float g_spk1[BATCH * 1024];
__device__ int          g_count;
__device__ volatile int g_gen;

struct Smem {
    float w0[8 * 512];          // [jl][k]  own 8 cols of W0
    float w1[8 * 1024];         // [jl][k]  own 8 cols of W1
    float w2[4 * 1024];         // [jl][k]  own 4 cols of W2
    float a[2][BATCH * APAD];   // double-buffered A chunks [b][64k]
    float mem0[BATCH * 8], spk0[BATCH * 8];
    float mem1[BATCH * 8], spk1[BATCH * 8];
    float mem2[BATCH * 4], spk2[BATCH * 4];
};

// ---- cp.async helpers ----
__device__ __forceinline__ void cp_async16(void* sdst, const void* gsrc) {
    uint32_t s = (uint32_t)__cvta_generic_to_shared(sdst);
    asm volatile("cp.async.cg.shared.global [%0], [%1], 16;" :: "r"(s), "l"(gsrc) : "memory");
}
__device__ __forceinline__ void cp_commit() {
    asm volatile("cp.async.commit_group;" ::: "memory");
}
__device__ __forceinline__ void cp_wait1() {
    asm volatile("cp.async.wait_group 1;" ::: "memory");
}

// ---- grid barrier: 128 CTAs, 1/SM, co-resident by construction ----
__device__ __forceinline__ void grid_sync()
{
    __threadfence();
    __syncthreads();
    if (threadIdx.x == 0) {
        int gen = g_gen;
        if (atomicAdd(&g_count, 1) == NCTA - 1) {
            g_count = 0;
            __threadfence();
            g_gen = gen + 1;
        } else {
            while (g_gen == gen) { }
        }
    }
    __syncthreads();
    __threadfence();
}

// One layer phase for this CTA's column slice.
// C = cols per CTA (= per thread, bb=1), K = reduction dim (chunks of 64).
// A rows streamed from global via double-buffered cp.async; W resident in smem.
template<int C, int K>
__device__ __forceinline__ void layer_phase(
    Smem* __restrict__ sm,
    const float* __restrict__ Aglob, int Astride,
    const float* __restrict__ Ws,
    float* __restrict__ memS, float* __restrict__ spkS,
    float* __restrict__ spkOut, int outStride, int jbase)
{
    const int tid = threadIdx.x;          // tid == batch row b
    constexpr int NC = K / 64;

    float acc[C];
#pragma unroll
    for (int j = 0; j < C; ++j) acc[j] = 0.0f;

    // prologue: issue chunk 0
#pragma unroll
    for (int i = 0; i < 16; ++i) {
        int flat = tid + i * NTHR;
        int br = flat >> 4, k4 = flat & 15;
        cp_async16(&sm->a[0][br * APAD + k4 * 4], Aglob + br * Astride + k4 * 4);
    }
    cp_commit();

    for (int c = 0; c < NC; ++c) {
        if (c + 1 < NC) {
            const float* src = Aglob + (c + 1) * 64;
#pragma unroll
            for (int i = 0; i < 16; ++i) {
                int flat = tid + i * NTHR;
                int br = flat >> 4, k4 = flat & 15;
                cp_async16(&sm->a[(c + 1) & 1][br * APAD + k4 * 4], src + br * Astride + k4 * 4);
            }
        }
        cp_commit();
        cp_wait1();                 // chunk c fully landed; c+1 in flight
        __syncthreads();

        const float4* A4 = (const float4*)sm->a[c & 1];
        const float4* W4 = (const float4*)Ws;
#pragma unroll
        for (int k4 = 0; k4 < 16; ++k4) {
            float4 av = A4[tid * (APAD / 4) + k4];      // distinct addr, conflict-free
#pragma unroll
            for (int j = 0; j < C; ++j) {
                float4 wv = W4[j * (K / 4) + c * 16 + k4];  // warp-uniform broadcast
                acc[j] = fmaf(av.x, wv.x, acc[j]);
                acc[j] = fmaf(av.y, wv.y, acc[j]);
                acc[j] = fmaf(av.z, wv.z, acc[j]);
                acc[j] = fmaf(av.w, wv.w, acc[j]);
            }
        }
        __syncthreads();            // all readers done before buffer reuse
    }

    // LIF update: mem*0.5*(1-s) exact (factor in {0,0.5}); one rounded add.
#pragma unroll
    for (int j = 0; j < C; ++j) {
        int idx = tid * C + j;
        float m  = memS[idx];
        float s  = spkS[idx];
        float nm = m * (0.5f * (1.0f - s)) + acc[j];
        float ns = (nm > 0.3f) ? 1.0f : 0.0f;
        memS[idx] = nm;
        spkS[idx] = ns;
        if (spkOut) spkOut[tid * outStride + jbase + j] = ns;
    }
}

__global__ __launch_bounds__(NTHR, 1)
void snn_kernel(const float* __restrict__ x,
                const float* __restrict__ w0,
                const float* __restrict__ w1,
                const float* __restrict__ w2,
                float* __restrict__ out)
{
    extern __shared__ char smem_raw[];
    Smem* sm = (Smem*)smem_raw;
    const int cta = blockIdx.x;
    const int tid = threadIdx.x;

    // ---- load this CTA's weight column slices into smem (one-time) ----
    for (int i = tid; i < 8 * 512; i += NTHR) {
        int k = i >> 3, jl = i & 7;
        sm->w0[jl * 512 + k] = w0[k * 1024 + cta * 8 + jl];
    }
    for (int i = tid; i < 8 * 1024; i += NTHR) {
        int k = i >> 3, jl = i & 7;
        sm->w1[jl * 1024 + k] = w1[k * 1024 + cta * 8 + jl];
    }
    for (int i = tid; i < 4 * 1024; i += NTHR) {
        int k = i >> 2, jl = i & 3;
        sm->w2[jl * 1024 + k] = w2[k * 512 + cta * 4 + jl];
    }
    // ---- zero private LIF state ----
    for (int i = tid; i < BATCH * 8; i += NTHR) {
        sm->mem0[i] = 0.f; sm->spk0[i] = 0.f;
        sm->mem1[i] = 0.f; sm->spk1[i] = 0.f;
    }
    for (int i = tid; i < BATCH * 4; i += NTHR) {
        sm->mem2[i] = 0.f; sm->spk2[i] = 0.f;
    }

    // ---- transpose x[b][k][t] -> g_xT[t][b][k] (32x32 smem tiles) ----
    {
        float* tile = sm->a[0];            // reuse: needs 32*33 floats
        const int r = tid >> 5, c = tid & 31;
        for (int tl = cta; tl < BATCH * 256; tl += NCTA) {   // uniform per-CTA count
            int b   = tl >> 8;
            int rem = tl & 255;
            int k0  = (rem >> 4) << 5;
            int t0  = (rem & 15) << 5;
            const float* src = x + (size_t)b * (512 * 512);
            __syncthreads();
            for (int rr = r; rr < 32; rr += 4)
                tile[rr * 33 + c] = src[(k0 + rr) * 512 + (t0 + c)];
            __syncthreads();
            for (int rr = r; rr < 32; rr += 4)
                g_xT[(size_t)(t0 + rr) * (BATCH * 512) + b * 512 + (k0 + c)] = tile[c * 33 + rr];
        }
    }
    grid_sync();

    // ---- time loop: phase1 = L0(t) || L2(t-1); phase2 = L1(t) ----
    for (int t = 0; t < T_STEPS; ++t) {
        layer_phase<8, 512>(sm, g_xT + (size_t)t * (BATCH * 512), 512,
                            sm->w0, sm->mem0, sm->spk0, g_spk0, 1024, cta * 8);
        if (t > 0)
            layer_phase<4, 1024>(sm, g_spk1, 1024,
                                 sm->w2, sm->mem2, sm->spk2, (float*)0, 0, 0);
        grid_sync();
        layer_phase<8, 1024>(sm, g_spk0, 1024,
                             sm->w1, sm->mem1, sm->spk1, g_spk1, 1024, cta * 8);
        grid_sync();
    }
    // final L2 step writes its spikes straight to the output
    layer_phase<4, 1024>(sm, g_spk1, 1024,
                         sm->w2, sm->mem2, sm->spk2, out, 512, cta * 4);
}

extern "C" void kernel_launch(void* const* d_in, const int* in_sizes, int n_in,
                              void* d_out, int out_size)
{
    const float* x  = (const float*)d_in[0];
    const float* w0 = (const float*)d_in[1];
    const float* w1 = (const float*)d_in[2];
    const float* w2 = (const float*)d_in[3];
    (void)in_sizes; (void)n_in; (void)out_size;

    int smemBytes = (int)sizeof(Smem);   // ~152 KB, needs opt-in
    cudaFuncSetAttribute(snn_kernel, cudaFuncAttributeMaxDynamicSharedMemorySize, smemBytes);
    snn_kernel<<<NCTA, NTHR, smemBytes>>>(x, w0, w1, w2, (float*)d_out);
}

// round 9
// speedup vs baseline: 1.7187x; 1.5773x over previous
#include <cuda_runtime.h>
#include <cstdint>

#define NCTA  128
#define NTHR  128
#define T_STEPS 512
#define BATCH 128
#define APAD  68      // staged A row: 64 floats + 4 pad (bank-conflict-free LDS.128)

// ---- global scratch (static: no allocation allowed) ----
__device__ float g_xT[T_STEPS * BATCH * 512];   // [t][b][k]  time-major input
__device__ float g_spk0[BATCH * 1024];
__device__ float g_spk1[BATCH * 1024];
__device__ int          g_count;
__device__ volatile int g_gen;

struct Smem {
    float w0[8 * 512];          // [jl][k]  own 8 cols of W0
    float w1[8 * 1024];         // [jl][k]  own 8 cols of W1
    float w2[4 * 1024];         // [jl][k]  own 4 cols of W2
    float a[2][BATCH * APAD];   // double-buffered A chunks [b][64k]
    float mem0[BATCH * 8], spk0[BATCH * 8];
    float mem1[BATCH * 8], spk1[BATCH * 8];
    float mem2[BATCH * 4], spk2[BATCH * 4];
};

// ---- cp.async helpers ----
__device__ __forceinline__ void cp_async16(void* sdst, const void* gsrc) {
    uint32_t s = (uint32_t)__cvta_generic_to_shared(sdst);
    asm volatile("cp.async.cg.shared.global [%0], [%1], 16;" :: "r"(s), "l"(gsrc) : "memory");
}
__device__ __forceinline__ void cp_commit() {
    asm volatile("cp.async.commit_group;" ::: "memory");
}
__device__ __forceinline__ void cp_wait1() {
    asm volatile("cp.async.wait_group 1;" ::: "memory");
}

// ---- grid barrier: 128 CTAs, 1/SM, co-resident by construction ----
__device__ __forceinline__ void grid_sync()
{
    __threadfence();
    __syncthreads();
    if (threadIdx.x == 0) {
        int gen = g_gen;
        if (atomicAdd(&g_count, 1) == NCTA - 1) {
            g_count = 0;
            __threadfence();
            g_gen = gen + 1;
        } else {
            while (g_gen == gen) { }
        }
    }
    __syncthreads();
    __threadfence();
}

// One layer phase for this CTA's column slice.
// C = cols per CTA (= per thread, bb=1), K = reduction dim (chunks of 64).
// A rows streamed from global via double-buffered cp.async; W resident in smem.
template<int C, int K>
__device__ __forceinline__ void layer_phase(
    Smem* __restrict__ sm,
    const float* __restrict__ Aglob, int Astride,
    const float* __restrict__ Ws,
    float* __restrict__ memS, float* __restrict__ spkS,
    float* __restrict__ spkOut, int outStride, int jbase)
{
    const int tid = threadIdx.x;          // tid == batch row b
    constexpr int NC = K / 64;

    float acc[C];
#pragma unroll
    for (int j = 0; j < C; ++j) acc[j] = 0.0f;

    // prologue: issue chunk 0
#pragma unroll
    for (int i = 0; i < 16; ++i) {
        int flat = tid + i * NTHR;
        int br = flat >> 4, k4 = flat & 15;
        cp_async16(&sm->a[0][br * APAD + k4 * 4], Aglob + br * Astride + k4 * 4);
    }
    cp_commit();

    for (int c = 0; c < NC; ++c) {
        if (c + 1 < NC) {
            const float* src = Aglob + (c + 1) * 64;
#pragma unroll
            for (int i = 0; i < 16; ++i) {
                int flat = tid + i * NTHR;
                int br = flat >> 4, k4 = flat & 15;
                cp_async16(&sm->a[(c + 1) & 1][br * APAD + k4 * 4], src + br * Astride + k4 * 4);
            }
        }
        cp_commit();
        cp_wait1();                 // chunk c fully landed; c+1 in flight
        __syncthreads();

        const float4* A4 = (const float4*)sm->a[c & 1];
        const float4* W4 = (const float4*)Ws;
#pragma unroll
        for (int k4 = 0; k4 < 16; ++k4) {
            float4 av = A4[tid * (APAD / 4) + k4];      // distinct addr, conflict-free
#pragma unroll
            for (int j = 0; j < C; ++j) {
                float4 wv = W4[j * (K / 4) + c * 16 + k4];  // warp-uniform broadcast
                acc[j] = fmaf(av.x, wv.x, acc[j]);
                acc[j] = fmaf(av.y, wv.y, acc[j]);
                acc[j] = fmaf(av.z, wv.z, acc[j]);
                acc[j] = fmaf(av.w, wv.w, acc[j]);
            }
        }
        __syncthreads();            // all readers done before buffer reuse
    }

    // LIF update: mem*0.5*(1-s) exact (factor in {0,0.5}); one rounded add.
#pragma unroll
    for (int j = 0; j < C; ++j) {
        int idx = tid * C + j;
        float m  = memS[idx];
        float s  = spkS[idx];
        float nm = m * (0.5f * (1.0f - s)) + acc[j];
        float ns = (nm > 0.3f) ? 1.0f : 0.0f;
        memS[idx] = nm;
        spkS[idx] = ns;
        if (spkOut) spkOut[tid * outStride + jbase + j] = ns;
    }
}

__global__ __launch_bounds__(NTHR, 1)
void snn_kernel(const float* __restrict__ x,
                const float* __restrict__ w0,
                const float* __restrict__ w1,
                const float* __restrict__ w2,
                float* __restrict__ out)
{
    extern __shared__ char smem_raw[];
    Smem* sm = (Smem*)smem_raw;
    const int cta = blockIdx.x;
    const int tid = threadIdx.x;

    // ---- load this CTA's weight column slices into smem (one-time) ----
    for (int i = tid; i < 8 * 512; i += NTHR) {
        int k = i >> 3, jl = i & 7;
        sm->w0[jl * 512 + k] = w0[k * 1024 + cta * 8 + jl];
    }
    for (int i = tid; i < 8 * 1024; i += NTHR) {
        int k = i >> 3, jl = i & 7;
        sm->w1[jl * 1024 + k] = w1[k * 1024 + cta * 8 + jl];
    }
    for (int i = tid; i < 4 * 1024; i += NTHR) {
        int k = i >> 2, jl = i & 3;
        sm->w2[jl * 1024 + k] = w2[k * 512 + cta * 4 + jl];
    }
    // ---- zero private LIF state ----
    for (int i = tid; i < BATCH * 8; i += NTHR) {
        sm->mem0[i] = 0.f; sm->spk0[i] = 0.f;
        sm->mem1[i] = 0.f; sm->spk1[i] = 0.f;
    }
    for (int i = tid; i < BATCH * 4; i += NTHR) {
        sm->mem2[i] = 0.f; sm->spk2[i] = 0.f;
    }

    // ---- transpose x[b][k][t] -> g_xT[t][b][k] (32x32 smem tiles) ----
    {
        float* tile = sm->a[0];            // reuse: needs 32*33 floats
        const int r = tid >> 5, c = tid & 31;
        for (int tl = cta; tl < BATCH * 256; tl += NCTA) {   // uniform per-CTA count
            int b   = tl >> 8;
            int rem = tl & 255;
            int k0  = (rem >> 4) << 5;
            int t0  = (rem & 15) << 5;
            const float* src = x + (size_t)b * (512 * 512);
            __syncthreads();
            for (int rr = r; rr < 32; rr += 4)
                tile[rr * 33 + c] = src[(k0 + rr) * 512 + (t0 + c)];
            __syncthreads();
            for (int rr = r; rr < 32; rr += 4)
                g_xT[(size_t)(t0 + rr) * (BATCH * 512) + b * 512 + (k0 + c)] = tile[c * 33 + rr];
        }
    }
    grid_sync();

    // ---- time loop: phase1 = L0(t) || L2(t-1); phase2 = L1(t) ----
    for (int t = 0; t < T_STEPS; ++t) {
        layer_phase<8, 512>(sm, g_xT + (size_t)t * (BATCH * 512), 512,
                            sm->w0, sm->mem0, sm->spk0, g_spk0, 1024, cta * 8);
        if (t > 0)
            layer_phase<4, 1024>(sm, g_spk1, 1024,
                                 sm->w2, sm->mem2, sm->spk2, (float*)0, 0, 0);
        grid_sync();
        layer_phase<8, 1024>(sm, g_spk0, 1024,
                             sm->w1, sm->mem1, sm->spk1, g_spk1, 1024, cta * 8);
        grid_sync();
    }
    // final L2 step writes its spikes straight to the output
    layer_phase<4, 1024>(sm, g_spk1, 1024,
                         sm->w2, sm->mem2, sm->spk2, out, 512, cta * 4);
}

extern "C" void kernel_launch(void* const* d_in, const int* in_sizes, int n_in,
                              void* d_out, int out_size)
{
    const float* x  = (const float*)d_in[0];
    const float* w0 = (const float*)d_in[1];
    const float* w1 = (const float*)d_in[2];
    const float* w2 = (const float*)d_in[3];
    (void)in_sizes; (void)n_in; (void)out_size;

    int smemBytes = (int)sizeof(Smem);   // ~152 KB, needs opt-in
    cudaFuncSetAttribute(snn_kernel, cudaFuncAttributeMaxDynamicSharedMemorySize, smemBytes);
    snn_kernel<<<NCTA, NTHR, smemBytes>>>(x, w0, w1, w2, (float*)d_out);
}